// round 2
// baseline (speedup 1.0000x reference)
#include <cuda_runtime.h>
#include <cstdint>

// Problem dims (fixed by the dataset)
#define N_SAMPLES 4096
#define D_BASES   64
#define I_IN      512
#define O_OUT     512
#define K_TOTAL   (D_BASES * I_IN)   // 32768

// GEMM tiling
#define BM 128
#define BN 128
#define BK 8
#define NTHREADS 512

// ---------------------------------------------------------------------------
// Packed f32x2 helpers (Blackwell sm_100a+): 2 fp32 FMAs per instruction.
// ---------------------------------------------------------------------------
__device__ __forceinline__ unsigned long long pack2(float x, float y) {
    unsigned long long r;
    asm("mov.b64 %0, {%1, %2};" : "=l"(r) : "f"(x), "f"(y));
    return r;
}
__device__ __forceinline__ void unpack2(unsigned long long v, float& x, float& y) {
    asm("mov.b64 {%0, %1}, %2;" : "=f"(x), "=f"(y) : "l"(v));
}
__device__ __forceinline__ unsigned long long fma2(unsigned long long a,
                                                   unsigned long long b,
                                                   unsigned long long c) {
    unsigned long long d;
    asm("fma.rn.f32x2 %0, %1, %2, %3;" : "=l"(d) : "l"(a), "l"(b), "l"(c));
    return d;
}

// ---------------------------------------------------------------------------
// Fused kernel: out = Z @ W_flat + var @ b
//   Z[n, k]      = var[n, k>>9] * x[n, k&511]   (generated on the fly)
//   W_flat[k, o] = W_1 viewed as [D*I, O] row-major (contiguous as given)
// One CTA computes a 128x128 output tile. 512 threads; each thread owns an
// 8-row x 4-col micro-tile held as 4x4 packed f32x2 accumulators (row pairs).
// ---------------------------------------------------------------------------
__global__ __launch_bounds__(NTHREADS, 1)
void mlp_param_fused_kernel(const float* __restrict__ x,
                            const float* __restrict__ var,
                            const float* __restrict__ W,
                            const float* __restrict__ b1,
                            float* __restrict__ out)
{
    __shared__ float As[BK][BM];     // Z tile, transposed: As[k][m]
    __shared__ float Bs[BK][BN];     // W tile: Bs[k][n]
    __shared__ float Vs[BM][65];     // var tile (padded to kill bank conflicts)

    const int tid = threadIdx.x;
    const int tx  = tid & 31;        // 0..31 -> output col base tx*4
    const int ty  = tid >> 5;        // 0..15 -> output row base ty*8
    const int gr0 = blockIdx.y * BM; // sample-row block
    const int gc0 = blockIdx.x * BN; // output-col block

    // Stage the var tile [128 x 64] into shared once.
    for (int idx = tid; idx < BM * D_BASES; idx += NTHREADS) {
        const int r = idx >> 6;
        const int c = idx & 63;
        Vs[r][c] = var[(gr0 + r) * D_BASES + c];
    }
    __syncthreads();

    // Global-load assignments (coalesced float2 per thread):
    const int ar = tid >> 2;          // 0..127 : A row
    const int ac = (tid & 3) * 2;     // 0,2,4,6: A cols (within BK)
    const int br = tid >> 6;          // 0..7   : B row (within BK)
    const int bc = (tid & 63) * 2;    // 0..126 : B cols

    const float* xrow = x + (gr0 + ar) * I_IN;
    const float* wcol = W + gc0 + bc;

    unsigned long long acc[4][4];     // [row-pair][col] packed f32x2
#pragma unroll
    for (int i = 0; i < 4; ++i)
#pragma unroll
        for (int j = 0; j < 4; ++j) acc[i][j] = 0ULL;

    // Prefetch k-block 0
    float2 aReg, bReg;
    {
        aReg = *reinterpret_cast<const float2*>(xrow + ac);
        const float v = Vs[ar][0];
        aReg.x *= v; aReg.y *= v;
        bReg = *reinterpret_cast<const float2*>(wcol + br * O_OUT);
    }

    const int NKB = K_TOTAL / BK;     // 4096 k-blocks
#pragma unroll 1
    for (int kb = 0; kb < NKB; ++kb) {
        __syncthreads();
        As[ac][ar]     = aReg.x;
        As[ac + 1][ar] = aReg.y;
        *reinterpret_cast<float2*>(&Bs[br][bc]) = bReg;
        __syncthreads();

        // Prefetch next k-block while computing this one.
        if (kb + 1 < NKB) {
            const int knext = (kb + 1) * BK;
            const int d  = knext >> 9;        // basis index (fixed within block)
            const int i0 = knext & (I_IN - 1);
            aReg = *reinterpret_cast<const float2*>(xrow + i0 + ac);
            const float v = Vs[ar][d];
            aReg.x *= v; aReg.y *= v;
            bReg = *reinterpret_cast<const float2*>(wcol + (knext + br) * O_OUT);
        }

#pragma unroll
        for (int kk = 0; kk < BK; ++kk) {
            const float4 bv = *reinterpret_cast<const float4*>(&Bs[kk][tx * 4]);
            unsigned long long b2[4];
            b2[0] = pack2(bv.x, bv.x);
            b2[1] = pack2(bv.y, bv.y);
            b2[2] = pack2(bv.z, bv.z);
            b2[3] = pack2(bv.w, bv.w);
            // Row pairs: two LDS.128 pulls 8 consecutive rows as 4 packed pairs.
            const ulonglong2 av0 = *reinterpret_cast<const ulonglong2*>(&As[kk][ty * 8]);
            const ulonglong2 av1 = *reinterpret_cast<const ulonglong2*>(&As[kk][ty * 8 + 4]);
            const unsigned long long a2[4] = {av0.x, av0.y, av1.x, av1.y};
#pragma unroll
            for (int i = 0; i < 4; ++i)
#pragma unroll
                for (int j = 0; j < 4; ++j)
                    acc[i][j] = fma2(a2[i], b2[j], acc[i][j]);
        }
    }

    // Unpack accumulators into per-row scalars.
    float accf[8][4];
#pragma unroll
    for (int i = 0; i < 4; ++i)
#pragma unroll
        for (int j = 0; j < 4; ++j)
            unpack2(acc[i][j], accf[2 * i][j], accf[2 * i + 1][j]);

    // Bias epilogue: accf[r][j] += sum_d var[row, d] * b1[d, col].
    const int gc = gc0 + tx * 4;
#pragma unroll 1
    for (int d = 0; d < D_BASES; ++d) {
        const float4 bb = *reinterpret_cast<const float4*>(b1 + d * O_OUT + gc);
#pragma unroll
        for (int r = 0; r < 8; ++r) {
            const float v = Vs[ty * 8 + r][d];
            accf[r][0] += v * bb.x;
            accf[r][1] += v * bb.y;
            accf[r][2] += v * bb.z;
            accf[r][3] += v * bb.w;
        }
    }

    // Store 8 rows x float4.
#pragma unroll
    for (int r = 0; r < 8; ++r) {
        float4 o;
        o.x = accf[r][0]; o.y = accf[r][1]; o.z = accf[r][2]; o.w = accf[r][3];
        *reinterpret_cast<float4*>(out + (gr0 + ty * 8 + r) * O_OUT + gc) = o;
    }
}

extern "C" void kernel_launch(void* const* d_in, const int* in_sizes, int n_in,
                              void* d_out, int out_size)
{
    const float* x   = (const float*)d_in[0];  // [4096, 512]
    const float* var = (const float*)d_in[1];  // [4096, 64]
    const float* W   = (const float*)d_in[2];  // [64, 512, 512] == [32768, 512]
    const float* b1  = (const float*)d_in[3];  // [64, 512]
    float* out = (float*)d_out;                // [4096, 512]

    dim3 grid(O_OUT / BN, N_SAMPLES / BM);     // 4 x 32 = 128 CTAs
    mlp_param_fused_kernel<<<grid, NTHREADS>>>(x, var, W, b1, out);
}

// round 4
// speedup vs baseline: 2.9027x; 2.9027x over previous
#include <cuda_runtime.h>
#include <cuda_bf16.h>
#include <cstdint>

// ---------------------------------------------------------------------------
// out[n,o] = sum_{d,i} var[n,d] x[n,i] W[d,i,o] + sum_d var[n,d] b[d,o]
//  == GEMM  out = Z @ B'   with K' = i*64 + d  (d fastest), K_EXT = 513*64:
//   Z[n, i*64+d]  = var[n,d] * x[n,i]   (i < 512)
//   Z[n, 32768+d] = var[n,d]            (bias stage, x == 1)
//   B'[i*64+d, o] = W[d,i,o] ; B'[32768+d, o] = b[d,o]
// bf16 split precision on HMMA (mma.sync.m16n8k16):
//   D = Ah*Bh + Al*Bh + Ah*Bl   (fp32 accumulate)
// ---------------------------------------------------------------------------

#define N_SAMPLES 4096
#define D_BASES   64
#define I_IN      512
#define O_OUT     512
#define K_EXT     32832
#define NSTAGE    513            // stage s == input column i (512 = bias)
#define BM        128
#define BN        128
#define BK        64
#define NTHREADS  256

#define ROW_BYTES 144            // 64 bf16 = 128B + 16B pad (conflict-free)
#define MAT_BYTES (128 * ROW_BYTES)          // 18432
#define A_HI 0
#define A_LO (1 * MAT_BYTES)
#define B_HI (2 * MAT_BYTES)
#define B_LO (3 * MAT_BYTES)
#define BUF_BYTES (4 * MAT_BYTES)            // 73728
#define NBUF 3
#define SMEM_TOTAL (NBUF * BUF_BYTES)        // 221184

// Pre-split transposed weights: [o][k'] rows, K-major
__device__ __nv_bfloat16 g_WT_hi[(size_t)O_OUT * K_EXT];
__device__ __nv_bfloat16 g_WT_lo[(size_t)O_OUT * K_EXT];

// ---------------------------------------------------------------------------
__device__ __forceinline__ uint32_t smem_u32(const void* p) {
    uint32_t a;
    asm("{ .reg .u64 t; cvta.to.shared.u64 t, %1; cvt.u32.u64 %0, t; }"
        : "=r"(a) : "l"(p));
    return a;
}
__device__ __forceinline__ void cp_async16(uint32_t dst, const void* src) {
    asm volatile("cp.async.cg.shared.global [%0], [%1], 16;"
                 :: "r"(dst), "l"(src));
}
__device__ __forceinline__ void cp_commit() {
    asm volatile("cp.async.commit_group;" ::: "memory");
}
__device__ __forceinline__ void cp_wait2() {
    asm volatile("cp.async.wait_group 2;" ::: "memory");
}
__device__ __forceinline__ void ldmx4(uint32_t* r, uint32_t addr) {
    asm volatile("ldmatrix.sync.aligned.m8n8.x4.shared.b16 {%0,%1,%2,%3}, [%4];"
                 : "=r"(r[0]), "=r"(r[1]), "=r"(r[2]), "=r"(r[3]) : "r"(addr));
}
__device__ __forceinline__ void mma16816(float* c, const uint32_t* a,
                                         const uint32_t* b) {
    asm volatile(
        "mma.sync.aligned.m16n8k16.row.col.f32.bf16.bf16.f32 "
        "{%0,%1,%2,%3}, {%4,%5,%6,%7}, {%8,%9}, {%0,%1,%2,%3};"
        : "+f"(c[0]), "+f"(c[1]), "+f"(c[2]), "+f"(c[3])
        : "r"(a[0]), "r"(a[1]), "r"(a[2]), "r"(a[3]), "r"(b[0]), "r"(b[1]));
}
// pack: f0 -> low half, f1 -> high half
__device__ __forceinline__ uint32_t cvt_bf16x2(float f0, float f1) {
    uint32_t r;
    asm("cvt.rn.bf16x2.f32 %0, %1, %2;" : "=r"(r) : "f"(f1), "f"(f0));
    return r;
}

// ---------------------------------------------------------------------------
// Prep: g_WT[o][i*64+d] = split(W[d][i][o]);  one block = (one i, 32 o's)
// ---------------------------------------------------------------------------
__global__ void prep_w_kernel(const float* __restrict__ W) {
    __shared__ float tile[64][33];
    const int i  = blockIdx.x;
    const int o0 = blockIdx.y * 32;
    const int t  = threadIdx.x;            // 256
    {
        const int d  = t >> 2;
        const int oc = (t & 3) * 8;
        const float* src = W + ((size_t)d * I_IN + i) * O_OUT + o0 + oc;
        const float4 v0 = *(const float4*)(src);
        const float4 v1 = *(const float4*)(src + 4);
        tile[d][oc + 0] = v0.x; tile[d][oc + 1] = v0.y;
        tile[d][oc + 2] = v0.z; tile[d][oc + 3] = v0.w;
        tile[d][oc + 4] = v1.x; tile[d][oc + 5] = v1.y;
        tile[d][oc + 6] = v1.z; tile[d][oc + 7] = v1.w;
    }
    __syncthreads();
    {
        const int ol = t >> 3;             // 0..31
        const int d0 = (t & 7) * 8;
        unsigned short hs[8], ls[8];
#pragma unroll
        for (int j = 0; j < 8; ++j) {
            const float f = tile[d0 + j][ol];
            const __nv_bfloat16 h = __float2bfloat16(f);
            const __nv_bfloat16 l = __float2bfloat16(f - __bfloat162float(h));
            hs[j] = *(const unsigned short*)&h;
            ls[j] = *(const unsigned short*)&l;
        }
        const size_t g = (size_t)(o0 + ol) * K_EXT + (size_t)i * 64 + d0;
        *(uint4*)(g_WT_hi + g) = *(const uint4*)hs;
        *(uint4*)(g_WT_lo + g) = *(const uint4*)ls;
    }
}

__global__ void prep_b_kernel(const float* __restrict__ b1) {
    const int o = blockIdx.x * 256 + threadIdx.x;
#pragma unroll 1
    for (int d = 0; d < D_BASES; ++d) {
        const float f = b1[d * O_OUT + o];
        const __nv_bfloat16 h = __float2bfloat16(f);
        const __nv_bfloat16 l = __float2bfloat16(f - __bfloat162float(h));
        const size_t g = (size_t)o * K_EXT + 32768 + d;
        g_WT_hi[g] = h;
        g_WT_lo[g] = l;
    }
}

// ---------------------------------------------------------------------------
// Main kernel: 128x128 tile/CTA, 8 warps (64x32 warp tiles), 3-buffer
// cp.async pipeline for B, register-built A, 3-pass split HMMA.
// ---------------------------------------------------------------------------
__global__ __launch_bounds__(NTHREADS, 1)
void mlp_mma_kernel(const float* __restrict__ x,
                    const float* __restrict__ var,
                    float* __restrict__ out)
{
    extern __shared__ char smem[];
    const uint32_t sbase = smem_u32(smem);
    const int tid  = threadIdx.x;
    const int wid  = tid >> 5;
    const int lane = tid & 31;
    const int gr0  = blockIdx.y * BM;
    const int gc0  = blockIdx.x * BN;

    // A-fill ownership: row am, d-halves [ah, ah+32)
    const int am = tid >> 1;
    const int ah = (tid & 1) * 32;

    // Preload this thread's 32 var values for the whole kernel.
    float vv[32];
    {
        const float4* vp = (const float4*)(var + (size_t)(gr0 + am) * D_BASES + ah);
#pragma unroll
        for (int q = 0; q < 8; ++q) {
            const float4 v = vp[q];
            vv[4 * q + 0] = v.x; vv[4 * q + 1] = v.y;
            vv[4 * q + 2] = v.z; vv[4 * q + 3] = v.w;
        }
    }

    auto loadx = [&](int s) -> float {
        if (s < I_IN) return __ldg(x + (size_t)(gr0 + am) * I_IN + s);
        return 1.0f;   // bias stage (or past-end prefetch, unused)
    };

    // B fill: 4 16B chunks per thread per dtype via cp.async
    auto fillB = [&](int s) {
        const uint32_t buf = sbase + (uint32_t)(s % NBUF) * BUF_BYTES;
#pragma unroll
        for (int t2 = 0; t2 < 4; ++t2) {
            const int c   = tid + t2 * NTHREADS;   // 0..1023
            const int row = c >> 3;
            const int col = c & 7;
            const uint32_t dst = buf + (uint32_t)(row * ROW_BYTES + col * 16);
            const size_t g = (size_t)(gc0 + row) * K_EXT + (size_t)s * 64 + col * 8;
            cp_async16(dst + B_HI, g_WT_hi + g);
            cp_async16(dst + B_LO, g_WT_lo + g);
        }
    };

    // A fill: split var*x into hi/lo bf16, STS 64B each
    auto fillA = [&](int s, float xv) {
        char* buf = smem + (size_t)(s % NBUF) * BUF_BYTES;
        uint32_t hw[16], lw[16];
#pragma unroll
        for (int j = 0; j < 16; ++j) {
            const float f0 = vv[2 * j] * xv;
            const float f1 = vv[2 * j + 1] * xv;
            const uint32_t h = cvt_bf16x2(f0, f1);
            const float h0 = __uint_as_float(h << 16);
            const float h1 = __uint_as_float(h & 0xFFFF0000u);
            hw[j] = h;
            lw[j] = cvt_bf16x2(f0 - h0, f1 - h1);
        }
        const int off = am * ROW_BYTES + ah * 2;
        uint4* dh = (uint4*)(buf + A_HI + off);
        uint4* dl = (uint4*)(buf + A_LO + off);
#pragma unroll
        for (int q = 0; q < 4; ++q) {
            dh[q] = make_uint4(hw[4*q], hw[4*q+1], hw[4*q+2], hw[4*q+3]);
            dl[q] = make_uint4(lw[4*q], lw[4*q+1], lw[4*q+2], lw[4*q+3]);
        }
    };

    // ---- prologue: stages 0 and 1
    fillB(0); fillA(0, loadx(0)); cp_commit();
    fillB(1); fillA(1, loadx(1)); cp_commit();
    float xv_pre = loadx(2);

    float acc[16][4];
#pragma unroll
    for (int i = 0; i < 16; ++i)
#pragma unroll
        for (int j = 0; j < 4; ++j) acc[i][j] = 0.0f;

    const int wm0 = (wid >> 2) * 64;
    const int wn0 = (wid & 3) * 32;

    // ldmatrix base offsets (lane-dependent, stage-invariant)
    const uint32_t a_lrow = (uint32_t)(lane & 15) * ROW_BYTES + ((lane >> 4) * 8) * 2;
    const uint32_t b_lrow = (uint32_t)((lane & 7) + ((lane >> 4) << 3)) * ROW_BYTES +
                            (((lane >> 3) & 1) * 8) * 2;

#pragma unroll 1
    for (int s = 0; s < NSTAGE; ++s) {
        __syncthreads();                    // everyone done reading buf (s-1)%3
        if (s + 2 < NSTAGE) {
            fillB(s + 2);
            fillA(s + 2, xv_pre);
        }
        xv_pre = loadx(s + 3);
        cp_commit();                        // (possibly empty) group
        cp_wait2();                         // stage s's B has landed
        __syncthreads();

        const uint32_t buf = sbase + (uint32_t)(s % NBUF) * BUF_BYTES;
        const uint32_t aBase = buf + A_HI + (uint32_t)(wm0 * ROW_BYTES) + a_lrow;
        const uint32_t bBase = buf + B_HI + (uint32_t)(wn0 * ROW_BYTES) + b_lrow;

#pragma unroll
        for (int ks = 0; ks < 4; ++ks) {
            const uint32_t koff = (uint32_t)(ks * 32);   // k0*2 bytes
            uint32_t aH[4][4], aL[4][4];
#pragma unroll
            for (int mt = 0; mt < 4; ++mt) {
                const uint32_t ad = aBase + (uint32_t)(mt * 16 * ROW_BYTES) + koff;
                ldmx4(aH[mt], ad);
                ldmx4(aL[mt], ad + MAT_BYTES);
            }
            uint32_t bH[4][2], bL[4][2];
#pragma unroll
            for (int nh = 0; nh < 2; ++nh) {
                const uint32_t bd = bBase + (uint32_t)(nh * 16 * ROW_BYTES) + koff;
                uint32_t r[4];
                ldmx4(r, bd + (B_HI - B_HI));
                bH[2*nh][0] = r[0]; bH[2*nh][1] = r[1];
                bH[2*nh+1][0] = r[2]; bH[2*nh+1][1] = r[3];
                ldmx4(r, bd + (B_LO - B_HI));
                bL[2*nh][0] = r[0]; bL[2*nh][1] = r[1];
                bL[2*nh+1][0] = r[2]; bL[2*nh+1][1] = r[3];
            }
#pragma unroll
            for (int mt = 0; mt < 4; ++mt)
#pragma unroll
                for (int nt = 0; nt < 4; ++nt) {
                    float* c = acc[mt * 4 + nt];
                    mma16816(c, aH[mt], bH[nt]);
                    mma16816(c, aL[mt], bH[nt]);
                    mma16816(c, aH[mt], bL[nt]);
                }
        }
    }

    // ---- epilogue: write fp32 results
#pragma unroll
    for (int mt = 0; mt < 4; ++mt) {
#pragma unroll
        for (int nt = 0; nt < 4; ++nt) {
            const float* c = acc[mt * 4 + nt];
            const int m = gr0 + wm0 + mt * 16 + (lane >> 2);
            const int n = gc0 + wn0 + nt * 8 + (lane & 3) * 2;
            *(float2*)(out + (size_t)m * O_OUT + n) = make_float2(c[0], c[1]);
            *(float2*)(out + (size_t)(m + 8) * O_OUT + n) = make_float2(c[2], c[3]);
        }
    }
}

// ---------------------------------------------------------------------------
extern "C" void kernel_launch(void* const* d_in, const int* in_sizes, int n_in,
                              void* d_out, int out_size)
{
    const float* x   = (const float*)d_in[0];  // [4096, 512]
    const float* var = (const float*)d_in[1];  // [4096, 64]
    const float* W   = (const float*)d_in[2];  // [64, 512, 512]
    const float* b1  = (const float*)d_in[3];  // [64, 512]
    float* out = (float*)d_out;                // [4096, 512]

    cudaFuncSetAttribute(mlp_mma_kernel,
                         cudaFuncAttributeMaxDynamicSharedMemorySize, SMEM_TOTAL);

    dim3 pg(I_IN, O_OUT / 32);                 // 512 x 16
    prep_w_kernel<<<pg, 256>>>(W);
    prep_b_kernel<<<O_OUT / 256, 256>>>(b1);

    dim3 grid(O_OUT / BN, N_SAMPLES / BM);     // 4 x 32 = 128 CTAs
    mlp_mma_kernel<<<grid, NTHREADS, SMEM_TOTAL>>>(x, var, out);
}

// round 5
// speedup vs baseline: 2.9064x; 1.0013x over previous
#include <cuda_runtime.h>
#include <cuda_bf16.h>
#include <cstdint>

// ---------------------------------------------------------------------------
// out[n,o] = sum_{d,i} var[n,d] x[n,i] W[d,i,o] + sum_d var[n,d] b[d,o]
//  == GEMM  out = Z @ B'   with K' = i*64 + d  (d fastest), K_EXT = 513*64:
//   Z[n, i*64+d]  = var[n,d] * x[n,i]   (i < 512)
//   Z[n, 32768+d] = var[n,d]            (bias stage, x == 1)
//   B'[i*64+d, o] = W[d,i,o] ; B'[32768+d, o] = b[d,o]
// bf16 split precision on HMMA (mma.sync.m16n8k16):
//   D = Ah*Bh + Al*Bh + Ah*Bl   (fp32 accumulate)
// ---------------------------------------------------------------------------

#define N_SAMPLES 4096
#define D_BASES   64
#define I_IN      512
#define O_OUT     512
#define K_EXT     32832
#define NSTAGE    513            // stage s == input column i (512 = bias)
#define BM        128
#define BN        128
#define BK        64
#define NTHREADS  256

#define ROW_BYTES 144            // 64 bf16 = 128B + 16B pad (conflict-free)
#define MAT_BYTES (128 * ROW_BYTES)          // 18432
#define A_HI 0
#define A_LO (1 * MAT_BYTES)
#define B_HI (2 * MAT_BYTES)
#define B_LO (3 * MAT_BYTES)
#define BUF_BYTES (4 * MAT_BYTES)            // 73728
#define NBUF 3
#define SMEM_TOTAL (NBUF * BUF_BYTES)        // 221184

// Pre-split transposed weights: [o][k'] rows, K-major
__device__ __nv_bfloat16 g_WT_hi[(size_t)O_OUT * K_EXT];
__device__ __nv_bfloat16 g_WT_lo[(size_t)O_OUT * K_EXT];

// ---------------------------------------------------------------------------
__device__ __forceinline__ uint32_t smem_u32(const void* p) {
    uint32_t a;
    asm("{ .reg .u64 t; cvta.to.shared.u64 t, %1; cvt.u32.u64 %0, t; }"
        : "=r"(a) : "l"(p));
    return a;
}
__device__ __forceinline__ void cp_async16(uint32_t dst, const void* src) {
    asm volatile("cp.async.cg.shared.global [%0], [%1], 16;"
                 :: "r"(dst), "l"(src));
}
__device__ __forceinline__ void cp_commit() {
    asm volatile("cp.async.commit_group;" ::: "memory");
}
__device__ __forceinline__ void cp_wait2() {
    asm volatile("cp.async.wait_group 2;" ::: "memory");
}
__device__ __forceinline__ void ldmx4(uint32_t* r, uint32_t addr) {
    asm volatile("ldmatrix.sync.aligned.m8n8.x4.shared.b16 {%0,%1,%2,%3}, [%4];"
                 : "=r"(r[0]), "=r"(r[1]), "=r"(r[2]), "=r"(r[3]) : "r"(addr));
}
__device__ __forceinline__ void mma16816(float* c, const uint32_t* a,
                                         const uint32_t* b) {
    asm volatile(
        "mma.sync.aligned.m16n8k16.row.col.f32.bf16.bf16.f32 "
        "{%0,%1,%2,%3}, {%4,%5,%6,%7}, {%8,%9}, {%0,%1,%2,%3};"
        : "+f"(c[0]), "+f"(c[1]), "+f"(c[2]), "+f"(c[3])
        : "r"(a[0]), "r"(a[1]), "r"(a[2]), "r"(a[3]), "r"(b[0]), "r"(b[1]));
}
// pack: f0 -> low half, f1 -> high half
__device__ __forceinline__ uint32_t cvt_bf16x2(float f0, float f1) {
    uint32_t r;
    asm("cvt.rn.bf16x2.f32 %0, %1, %2;" : "=r"(r) : "f"(f1), "f"(f0));
    return r;
}

// ---------------------------------------------------------------------------
// Prep: g_WT[o][i*64+d] = split(W[d][i][o]);  one block = (one i, 32 o's)
// ---------------------------------------------------------------------------
__global__ void prep_w_kernel(const float* __restrict__ W) {
    __shared__ float tile[64][33];
    const int i  = blockIdx.x;
    const int o0 = blockIdx.y * 32;
    const int t  = threadIdx.x;            // 256
    {
        const int d  = t >> 2;
        const int oc = (t & 3) * 8;
        const float* src = W + ((size_t)d * I_IN + i) * O_OUT + o0 + oc;
        const float4 v0 = *(const float4*)(src);
        const float4 v1 = *(const float4*)(src + 4);
        tile[d][oc + 0] = v0.x; tile[d][oc + 1] = v0.y;
        tile[d][oc + 2] = v0.z; tile[d][oc + 3] = v0.w;
        tile[d][oc + 4] = v1.x; tile[d][oc + 5] = v1.y;
        tile[d][oc + 6] = v1.z; tile[d][oc + 7] = v1.w;
    }
    __syncthreads();
    {
        const int ol = t >> 3;             // 0..31
        const int d0 = (t & 7) * 8;
        unsigned short hs[8], ls[8];
#pragma unroll
        for (int j = 0; j < 8; ++j) {
            const float f = tile[d0 + j][ol];
            const __nv_bfloat16 h = __float2bfloat16(f);
            const __nv_bfloat16 l = __float2bfloat16(f - __bfloat162float(h));
            hs[j] = *(const unsigned short*)&h;
            ls[j] = *(const unsigned short*)&l;
        }
        const size_t g = (size_t)(o0 + ol) * K_EXT + (size_t)i * 64 + d0;
        *(uint4*)(g_WT_hi + g) = *(const uint4*)hs;
        *(uint4*)(g_WT_lo + g) = *(const uint4*)ls;
    }
}

__global__ void prep_b_kernel(const float* __restrict__ b1) {
    const int o = blockIdx.x * 256 + threadIdx.x;
#pragma unroll 1
    for (int d = 0; d < D_BASES; ++d) {
        const float f = b1[d * O_OUT + o];
        const __nv_bfloat16 h = __float2bfloat16(f);
        const __nv_bfloat16 l = __float2bfloat16(f - __bfloat162float(h));
        const size_t g = (size_t)o * K_EXT + 32768 + d;
        g_WT_hi[g] = h;
        g_WT_lo[g] = l;
    }
}

// ---------------------------------------------------------------------------
// Main kernel: 128x128 tile/CTA, 8 warps (64x32 warp tiles), 3-buffer
// cp.async pipeline for B, register-built A, 3-pass split HMMA.
// ---------------------------------------------------------------------------
__global__ __launch_bounds__(NTHREADS, 1)
void mlp_mma_kernel(const float* __restrict__ x,
                    const float* __restrict__ var,
                    float* __restrict__ out)
{
    extern __shared__ char smem[];
    const uint32_t sbase = smem_u32(smem);
    const int tid  = threadIdx.x;
    const int wid  = tid >> 5;
    const int lane = tid & 31;
    const int gr0  = blockIdx.y * BM;
    const int gc0  = blockIdx.x * BN;

    // A-fill ownership: row am, d-halves [ah, ah+32)
    const int am = tid >> 1;
    const int ah = (tid & 1) * 32;

    // Preload this thread's 32 var values for the whole kernel.
    float vv[32];
    {
        const float4* vp = (const float4*)(var + (size_t)(gr0 + am) * D_BASES + ah);
#pragma unroll
        for (int q = 0; q < 8; ++q) {
            const float4 v = vp[q];
            vv[4 * q + 0] = v.x; vv[4 * q + 1] = v.y;
            vv[4 * q + 2] = v.z; vv[4 * q + 3] = v.w;
        }
    }

    auto loadx = [&](int s) -> float {
        if (s < I_IN) return __ldg(x + (size_t)(gr0 + am) * I_IN + s);
        return 1.0f;   // bias stage (or past-end prefetch, unused)
    };

    // B fill: 4 16B chunks per thread per dtype via cp.async
    auto fillB = [&](int s) {
        const uint32_t buf = sbase + (uint32_t)(s % NBUF) * BUF_BYTES;
#pragma unroll
        for (int t2 = 0; t2 < 4; ++t2) {
            const int c   = tid + t2 * NTHREADS;   // 0..1023
            const int row = c >> 3;
            const int col = c & 7;
            const uint32_t dst = buf + (uint32_t)(row * ROW_BYTES + col * 16);
            const size_t g = (size_t)(gc0 + row) * K_EXT + (size_t)s * 64 + col * 8;
            cp_async16(dst + B_HI, g_WT_hi + g);
            cp_async16(dst + B_LO, g_WT_lo + g);
        }
    };

    // A fill: split var*x into hi/lo bf16, STS 64B each
    auto fillA = [&](int s, float xv) {
        char* buf = smem + (size_t)(s % NBUF) * BUF_BYTES;
        uint32_t hw[16], lw[16];
#pragma unroll
        for (int j = 0; j < 16; ++j) {
            const float f0 = vv[2 * j] * xv;
            const float f1 = vv[2 * j + 1] * xv;
            const uint32_t h = cvt_bf16x2(f0, f1);
            const float h0 = __uint_as_float(h << 16);
            const float h1 = __uint_as_float(h & 0xFFFF0000u);
            hw[j] = h;
            lw[j] = cvt_bf16x2(f0 - h0, f1 - h1);
        }
        const int off = am * ROW_BYTES + ah * 2;
        uint4* dh = (uint4*)(buf + A_HI + off);
        uint4* dl = (uint4*)(buf + A_LO + off);
#pragma unroll
        for (int q = 0; q < 4; ++q) {
            dh[q] = make_uint4(hw[4*q], hw[4*q+1], hw[4*q+2], hw[4*q+3]);
            dl[q] = make_uint4(lw[4*q], lw[4*q+1], lw[4*q+2], lw[4*q+3]);
        }
    };

    // ---- prologue: stages 0 and 1
    fillB(0); fillA(0, loadx(0)); cp_commit();
    fillB(1); fillA(1, loadx(1)); cp_commit();
    float xv_pre = loadx(2);

    float acc[16][4];
#pragma unroll
    for (int i = 0; i < 16; ++i)
#pragma unroll
        for (int j = 0; j < 4; ++j) acc[i][j] = 0.0f;

    const int wm0 = (wid >> 2) * 64;
    const int wn0 = (wid & 3) * 32;

    // ldmatrix base offsets (lane-dependent, stage-invariant)
    const uint32_t a_lrow = (uint32_t)(lane & 15) * ROW_BYTES + ((lane >> 4) * 8) * 2;
    const uint32_t b_lrow = (uint32_t)((lane & 7) + ((lane >> 4) << 3)) * ROW_BYTES +
                            (((lane >> 3) & 1) * 8) * 2;

#pragma unroll 1
    for (int s = 0; s < NSTAGE; ++s) {
        __syncthreads();                    // everyone done reading buf (s-1)%3
        if (s + 2 < NSTAGE) {
            fillB(s + 2);
            fillA(s + 2, xv_pre);
        }
        xv_pre = loadx(s + 3);
        cp_commit();                        // (possibly empty) group
        cp_wait2();                         // stage s's B has landed
        __syncthreads();

        const uint32_t buf = sbase + (uint32_t)(s % NBUF) * BUF_BYTES;
        const uint32_t aBase = buf + A_HI + (uint32_t)(wm0 * ROW_BYTES) + a_lrow;
        const uint32_t bBase = buf + B_HI + (uint32_t)(wn0 * ROW_BYTES) + b_lrow;

#pragma unroll
        for (int ks = 0; ks < 4; ++ks) {
            const uint32_t koff = (uint32_t)(ks * 32);   // k0*2 bytes
            uint32_t aH[4][4], aL[4][4];
#pragma unroll
            for (int mt = 0; mt < 4; ++mt) {
                const uint32_t ad = aBase + (uint32_t)(mt * 16 * ROW_BYTES) + koff;
                ldmx4(aH[mt], ad);
                ldmx4(aL[mt], ad + MAT_BYTES);
            }
            uint32_t bH[4][2], bL[4][2];
#pragma unroll
            for (int nh = 0; nh < 2; ++nh) {
                const uint32_t bd = bBase + (uint32_t)(nh * 16 * ROW_BYTES) + koff;
                uint32_t r[4];
                ldmx4(r, bd + (B_HI - B_HI));
                bH[2*nh][0] = r[0]; bH[2*nh][1] = r[1];
                bH[2*nh+1][0] = r[2]; bH[2*nh+1][1] = r[3];
                ldmx4(r, bd + (B_LO - B_HI));
                bL[2*nh][0] = r[0]; bL[2*nh][1] = r[1];
                bL[2*nh+1][0] = r[2]; bL[2*nh+1][1] = r[3];
            }
#pragma unroll
            for (int mt = 0; mt < 4; ++mt)
#pragma unroll
                for (int nt = 0; nt < 4; ++nt) {
                    float* c = acc[mt * 4 + nt];
                    mma16816(c, aH[mt], bH[nt]);
                    mma16816(c, aL[mt], bH[nt]);
                    mma16816(c, aH[mt], bL[nt]);
                }
        }
    }

    // ---- epilogue: write fp32 results
#pragma unroll
    for (int mt = 0; mt < 4; ++mt) {
#pragma unroll
        for (int nt = 0; nt < 4; ++nt) {
            const float* c = acc[mt * 4 + nt];
            const int m = gr0 + wm0 + mt * 16 + (lane >> 2);
            const int n = gc0 + wn0 + nt * 8 + (lane & 3) * 2;
            *(float2*)(out + (size_t)m * O_OUT + n) = make_float2(c[0], c[1]);
            *(float2*)(out + (size_t)(m + 8) * O_OUT + n) = make_float2(c[2], c[3]);
        }
    }
}

// ---------------------------------------------------------------------------
extern "C" void kernel_launch(void* const* d_in, const int* in_sizes, int n_in,
                              void* d_out, int out_size)
{
    const float* x   = (const float*)d_in[0];  // [4096, 512]
    const float* var = (const float*)d_in[1];  // [4096, 64]
    const float* W   = (const float*)d_in[2];  // [64, 512, 512]
    const float* b1  = (const float*)d_in[3];  // [64, 512]
    float* out = (float*)d_out;                // [4096, 512]

    cudaFuncSetAttribute(mlp_mma_kernel,
                         cudaFuncAttributeMaxDynamicSharedMemorySize, SMEM_TOTAL);

    dim3 pg(I_IN, O_OUT / 32);                 // 512 x 16
    prep_w_kernel<<<pg, 256>>>(W);
    prep_b_kernel<<<O_OUT / 256, 256>>>(b1);

    dim3 grid(O_OUT / BN, N_SAMPLES / BM);     // 4 x 32 = 128 CTAs
    mlp_mma_kernel<<<grid, NTHREADS, SMEM_TOTAL>>>(x, var, out);
}